// round 13
// baseline (speedup 1.0000x reference)
#include <cuda_runtime.h>

// out[b,d,t] = T*x[b,d,t] - 2 * sum_{s ≡ t (mod 2)} x[b,d,s],  T = 1024.
// (Dirichlet-kernel collapse of the rfft -> cos/sin GEMM reference; see R1.)
//
// R12: R10 retry with the correct PTX encoding. Bare .L2::evict_last is
// 256-bit-only on this ptxas; the general form is createpolicy.fractional
// .L2::evict_last + ld/st.global.*.L2::cache_hint. Both 32MB streams fit the
// 126MB L2; pinning them evict_last lets dirty output lines be rewritten
// across graph replays instead of force-draining to DRAM every replay.
// Structure = R9 (persistent, 2 CTAs/SM, prefetch-before-reduce), unchanged.

#define ROW_LEN       1024
#define THREADS       256
#define WARPS_PER_CTA 8
#define GRID_CTAS     296        // 2 CTAs per SM, one wave
#define VEC_PER_LANE  8          // 8 float4 = 32 floats per lane

__device__ __forceinline__ unsigned long long make_evict_last_policy() {
    unsigned long long pol;
    asm volatile("createpolicy.fractional.L2::evict_last.b64 %0, 1.0;"
                 : "=l"(pol));
    return pol;
}

__device__ __forceinline__ float4 ld_el(const float4* p, unsigned long long pol) {
    float4 v;
    asm volatile("ld.global.nc.L2::cache_hint.v4.f32 {%0,%1,%2,%3}, [%4], %5;"
                 : "=f"(v.x), "=f"(v.y), "=f"(v.z), "=f"(v.w)
                 : "l"(p), "l"(pol));
    return v;
}

__device__ __forceinline__ void st_el(float4* p, float4 v, unsigned long long pol) {
    asm volatile("st.global.L2::cache_hint.v4.f32 [%0], {%1,%2,%3,%4}, %5;"
                 :: "l"(p), "f"(v.x), "f"(v.y), "f"(v.z), "f"(v.w), "l"(pol)
                 : "memory");
}

__device__ __forceinline__ void load_row(float4 v[VEC_PER_LANE],
                                         const float* __restrict__ x,
                                         int row, int lane,
                                         unsigned long long pol) {
    const float4* xr = reinterpret_cast<const float4*>(x)
                     + (size_t)row * (ROW_LEN / 4);
    #pragma unroll
    for (int j = 0; j < VEC_PER_LANE; j++)
        v[j] = ld_el(xr + lane + 32 * j, pol);
}

__device__ __forceinline__ void reduce_store(const float4 v[VEC_PER_LANE],
                                             float* __restrict__ out,
                                             int row, int lane,
                                             unsigned long long pol) {
    // Element index of v[j].x is 4*(lane+32j): .x/.z even, .y/.w odd.
    float esum = 0.0f, osum = 0.0f;
    #pragma unroll
    for (int j = 0; j < VEC_PER_LANE; j++) {
        esum += v[j].x + v[j].z;
        osum += v[j].y + v[j].w;
    }
    #pragma unroll
    for (int off = 16; off > 0; off >>= 1) {
        esum += __shfl_xor_sync(0xffffffffu, esum, off);
        osum += __shfl_xor_sync(0xffffffffu, osum, off);
    }
    const float E2 = 2.0f * esum;
    const float O2 = 2.0f * osum;
    const float T  = (float)ROW_LEN;

    float4* outr = reinterpret_cast<float4*>(out) + (size_t)row * (ROW_LEN / 4);
    #pragma unroll
    for (int j = 0; j < VEC_PER_LANE; j++) {
        float4 r;
        r.x = fmaf(T, v[j].x, -E2);
        r.y = fmaf(T, v[j].y, -O2);
        r.z = fmaf(T, v[j].z, -E2);
        r.w = fmaf(T, v[j].w, -O2);
        st_el(outr + lane + 32 * j, r, pol);
    }
}

__global__ __launch_bounds__(THREADS)
void season_block_46428596469890_kernel(const float* __restrict__ x,
                                        float* __restrict__ out, int n_rows) {
    const int lane = threadIdx.x & 31;
    const int warp = threadIdx.x >> 5;
    const int stride = GRID_CTAS * WARPS_PER_CTA;       // 2368
    int row = blockIdx.x * WARPS_PER_CTA + warp;
    if (row >= n_rows) return;

    const unsigned long long pol = make_evict_last_policy();

    float4 va[VEC_PER_LANE], vb[VEC_PER_LANE];
    load_row(va, x, row, lane, pol);

    for (;;) {
        int n1 = row + stride;
        if (n1 < n_rows) load_row(vb, x, n1, lane, pol);  // prefetch
        reduce_store(va, out, row, lane, pol);
        if (n1 >= n_rows) break;

        int n2 = n1 + stride;
        if (n2 < n_rows) load_row(va, x, n2, lane, pol);  // prefetch
        reduce_store(vb, out, n1, lane, pol);
        if (n2 >= n_rows) break;
        row = n2;
    }
}

extern "C" void kernel_launch(void* const* d_in, const int* in_sizes, int n_in,
                              void* d_out, int out_size) {
    const float* x = (const float*)d_in[0];
    float* out = (float*)d_out;
    const int n_rows = in_sizes[0] / ROW_LEN;           // 8192
    season_block_46428596469890_kernel<<<GRID_CTAS, THREADS>>>(x, out, n_rows);
}

// round 14
// speedup vs baseline: 1.0269x; 1.0269x over previous
#include <cuda_runtime.h>

// out[b,d,t] = T*x[b,d,t] - 2 * sum_{s ≡ t (mod 2)} x[b,d,s],  T = 1024.
// (Dirichlet-kernel collapse of the rfft -> cos/sin GEMM reference; see R1.)
//
// R13: R7 structure (warp-per-row, register-resident, shuffle-only reduce,
// evict-first streaming stores) with 256-bit memory ops (ld/st.global.v4.b64,
// revealed as supported by the R12 ptxas diagnostics). Same 64MB of L2
// traffic — the proven binder (LTS cap ~6.2TB/s across R5-R12) — but half
// the LSU/L1tex requests, recovering request-rate overhead at saturation.

#define ROW_LEN        1024
#define THREADS        256          // 8 warps -> 8 rows per block
#define V256_PER_LANE  4            // 4 x 256-bit = 32 floats per lane

struct V8 { unsigned long long a, b, c, d; };   // 8 packed floats

__device__ __forceinline__ V8 ld256(const void* p) {
    V8 v;
    asm volatile("ld.global.nc.v4.b64 {%0,%1,%2,%3}, [%4];"
                 : "=l"(v.a), "=l"(v.b), "=l"(v.c), "=l"(v.d) : "l"(p));
    return v;
}

__device__ __forceinline__ void st256_cs(void* p, const V8& v) {
    asm volatile("st.global.cs.v4.b64 [%0], {%1,%2,%3,%4};"
                 :: "l"(p), "l"(v.a), "l"(v.b), "l"(v.c), "l"(v.d) : "memory");
}

// lo half of each b64 = even element, hi half = odd element.
__device__ __forceinline__ void accum_pair(unsigned long long w,
                                           float& e, float& o) {
    e += __uint_as_float((unsigned)w);
    o += __uint_as_float((unsigned)(w >> 32));
}

__device__ __forceinline__ unsigned long long fma_pair(unsigned long long w,
                                                       float T, float E2,
                                                       float O2) {
    float lo = fmaf(T, __uint_as_float((unsigned)w),         -E2);
    float hi = fmaf(T, __uint_as_float((unsigned)(w >> 32)), -O2);
    return (unsigned long long)__float_as_uint(lo)
         | ((unsigned long long)__float_as_uint(hi) << 32);
}

__global__ __launch_bounds__(THREADS)
void season_block_46428596469890_kernel(const float* __restrict__ x,
                                        float* __restrict__ out) {
    const int lane = threadIdx.x & 31;
    const int warp = threadIdx.x >> 5;
    const long long row = (long long)blockIdx.x * 8 + warp;

    const char* xr = reinterpret_cast<const char*>(x) + row * (ROW_LEN * 4);
    char* outr     = reinterpret_cast<char*>(out)     + row * (ROW_LEN * 4);

    // Front-batched 256-bit loads: 4 per lane, 32B each.
    // Chunk j covers bytes [(j*32 + lane)*32, +32): element base (j*32+lane)*8.
    V8 v[V256_PER_LANE];
    #pragma unroll
    for (int j = 0; j < V256_PER_LANE; j++)
        v[j] = ld256(xr + ((size_t)(j * 32 + lane) << 5));

    // Even elements sit in lo halves, odd in hi halves (element base is
    // a multiple of 8, so parity within each b64 pair is fixed).
    float esum = 0.0f, osum = 0.0f;
    #pragma unroll
    for (int j = 0; j < V256_PER_LANE; j++) {
        accum_pair(v[j].a, esum, osum);
        accum_pair(v[j].b, esum, osum);
        accum_pair(v[j].c, esum, osum);
        accum_pair(v[j].d, esum, osum);
    }

    // Warp-only reduction; every lane ends with the full-row sums.
    #pragma unroll
    for (int off = 16; off > 0; off >>= 1) {
        esum += __shfl_xor_sync(0xffffffffu, esum, off);
        osum += __shfl_xor_sync(0xffffffffu, osum, off);
    }

    const float E2 = 2.0f * esum;
    const float O2 = 2.0f * osum;
    const float T  = (float)ROW_LEN;

    #pragma unroll
    for (int j = 0; j < V256_PER_LANE; j++) {
        V8 r;
        r.a = fma_pair(v[j].a, T, E2, O2);
        r.b = fma_pair(v[j].b, T, E2, O2);
        r.c = fma_pair(v[j].c, T, E2, O2);
        r.d = fma_pair(v[j].d, T, E2, O2);
        st256_cs(outr + ((size_t)(j * 32 + lane) << 5), r);
    }
}

extern "C" void kernel_launch(void* const* d_in, const int* in_sizes, int n_in,
                              void* d_out, int out_size) {
    const float* x = (const float*)d_in[0];
    float* out = (float*)d_out;
    const int n_rows = in_sizes[0] / ROW_LEN;       // 8192
    season_block_46428596469890_kernel<<<n_rows / 8, THREADS>>>(x, out);
}